// round 13
// baseline (speedup 1.0000x reference)
#include <cuda_runtime.h>

#define BB 2
#define CC 256
#define MID 128
#define NN 6272
#define NT 49
#define SPLITS 3
#define PAD 130

// -------- static scratch (no runtime allocation allowed) --------
__device__ float g_Q[BB * MID * NN];
__device__ float g_K[BB * MID * NN];
__device__ float g_V[BB * MID * NN];
__device__ float g_Op[SPLITS * BB * NT * 128 * 128];   // partial O, [s][b][qt][q][m]
__device__ float g_ml[SPLITS * BB * NT * 256];          // per row: [0..127]=m, [128..255]=l

// -------- packed f32x2 helpers (PTX-only; ptxas never auto-fuses) --------
__device__ __forceinline__ unsigned long long pack2(float lo, float hi) {
    unsigned long long r;
    asm("mov.b64 %0, {%1, %2};" : "=l"(r) : "f"(lo), "f"(hi));
    return r;
}
__device__ __forceinline__ void unpack2(unsigned long long v, float& lo, float& hi) {
    asm("mov.b64 {%0, %1}, %2;" : "=f"(lo), "=f"(hi) : "l"(v));
}
__device__ __forceinline__ void fma2(unsigned long long& d, unsigned long long a, unsigned long long b) {
    asm("fma.rn.f32x2 %0, %1, %2, %0;" : "+l"(d) : "l"(a), "l"(b));
}
__device__ __forceinline__ void mul2(unsigned long long& d, unsigned long long a) {
    asm("mul.rn.f32x2 %0, %0, %1;" : "+l"(d) : "l"(a));
}
__device__ __forceinline__ unsigned long long lds2(const float* p) {
    return *reinterpret_cast<const unsigned long long*>(p);
}
__device__ __forceinline__ float ninf() { return __int_as_float(0xff800000); }

// ============================================================================
// Phase 1: QKV projection. out[b][m][n] = bias[m] + sum_c w[m][c]*x[b][c][n]
// grid (49 ntiles, 12 mchunks-of-32 over 384, B), block 64 (2 n per thread)
// ============================================================================
__global__ void __launch_bounds__(64) proj_kernel(
    const float* __restrict__ x,
    const float* __restrict__ w1, const float* __restrict__ b1,
    const float* __restrict__ w2, const float* __restrict__ b2,
    const float* __restrict__ w3, const float* __restrict__ b3)
{
    __shared__ float wsm[CC][34];  // [c][j], pad 34 keeps 8B alignment + low conflicts
    const int nt = blockIdx.x;
    const int mg = blockIdx.y;
    const int b  = blockIdx.z;
    const int t  = threadIdx.x;

    const int mbase  = (mg & 3) * 32;
    const int which  = mg >> 2;
    const float* w   = (which == 0) ? w1 : ((which == 1) ? w2 : w3);
    const float* bb  = (which == 0) ? b1 : ((which == 1) ? b2 : b3);
    float* out       = (which == 0) ? g_Q : ((which == 1) ? g_K : g_V);

    for (int idx = t; idx < 32 * CC; idx += 64) {
        int j = idx >> 8;
        int c = idx & 255;
        wsm[c][j] = w[(mbase + j) * CC + c];
    }
    __syncthreads();

    const int n0 = nt * 128 + 2 * t;
    const float* xp = x + (b * CC) * NN + n0;

    unsigned long long acc0[16], acc1[16];
#pragma unroll
    for (int j = 0; j < 16; ++j) { acc0[j] = 0ULL; acc1[j] = 0ULL; }

#pragma unroll 4
    for (int c = 0; c < CC; ++c) {
        float2 xv = *reinterpret_cast<const float2*>(xp + c * NN);
        unsigned long long xa = pack2(xv.x, xv.x);
        unsigned long long xb = pack2(xv.y, xv.y);
#pragma unroll
        for (int j = 0; j < 16; ++j) {
            unsigned long long wv = lds2(&wsm[c][2 * j]);
            fma2(acc0[j], xa, wv);
            fma2(acc1[j], xb, wv);
        }
    }

#pragma unroll
    for (int j = 0; j < 16; ++j) {
        float a0, a1, c0, c1;
        unpack2(acc0[j], a0, a1);
        unpack2(acc1[j], c0, c1);
        int m0 = mbase + 2 * j;
        float bv0 = bb[m0], bv1 = bb[m0 + 1];
        int base0 = (b * MID + m0) * NN + n0;
        int base1 = (b * MID + m0 + 1) * NN + n0;
        out[base0]     = a0 + bv0;
        out[base0 + 1] = c0 + bv0;
        out[base1]     = a1 + bv1;
        out[base1 + 1] = c1 + bv1;
    }
}

// ============================================================================
// Phase 2: flash attention, split-K=3. grid (NT, B, SPLITS), 256 threads.
// smem: Qs[m][q] | KPs (K[m][k] then P[k][q]) | Vs[k][m], all rows padded to 130.
// Thread (tq=t>>4, tk=t&15): q rows tq*8..+7 (paired for f32x2), k/m cols tk+16u.
// ============================================================================
__global__ void __launch_bounds__(256, 1) attn_kernel()
{
    extern __shared__ float sm[];
    float* Qs  = sm;
    float* KPs = sm + 128 * PAD;
    float* Vs  = sm + 2 * 128 * PAD;

    const int qt = blockIdx.x;
    const int b  = blockIdx.y;
    const int sp = blockIdx.z;
    const int t  = threadIdx.x;
    const int tq = t >> 4;
    const int tk = t & 15;
    const int q0 = qt * 128;

    const float* Qb = g_Q + b * MID * NN;
    const float* Kb = g_K + b * MID * NN;
    const float* Vb = g_V + b * MID * NN;

    // Q tile: Qs[m][q]
    for (int idx = t; idx < 128 * 128; idx += 256) {
        int m = idx >> 7, q = idx & 127;
        Qs[m * PAD + q] = Qb[m * NN + q0 + q];
    }

    unsigned long long o2[8][4];
#pragma unroll
    for (int u = 0; u < 8; ++u)
#pragma unroll
        for (int i2 = 0; i2 < 4; ++i2) o2[u][i2] = 0ULL;
    float mrow[8], lrow[8];
#pragma unroll
    for (int i = 0; i < 8; ++i) { mrow[i] = ninf(); lrow[i] = 0.f; }

    const int kt0 = sp * 16 + (sp > 0 ? 1 : 0);
    const int kt1 = kt0 + (sp == 0 ? 17 : 16);

    for (int kt = kt0; kt < kt1; ++kt) {
        __syncthreads();  // protect KPs/Vs from previous-iter readers
        const int k0g = kt * 128;
        for (int idx = t; idx < 128 * 128; idx += 256) {
            int m = idx >> 7, k = idx & 127;
            KPs[m * PAD + k] = Kb[m * NN + k0g + k];
        }
        for (int idx = t; idx < 128 * 128; idx += 256) {
            int m = idx >> 7, k = idx & 127;
            Vs[k * PAD + m] = Vb[m * NN + k0g + k];  // transpose to [k][m]
        }
        __syncthreads();

        // ---- S = Q @ K^T ----
        unsigned long long s2[8][4];
#pragma unroll
        for (int u = 0; u < 8; ++u)
#pragma unroll
            for (int i2 = 0; i2 < 4; ++i2) s2[u][i2] = 0ULL;

#pragma unroll 4
        for (int m = 0; m < 128; ++m) {
            unsigned long long q2[4];
#pragma unroll
            for (int i2 = 0; i2 < 4; ++i2)
                q2[i2] = lds2(&Qs[m * PAD + tq * 8 + 2 * i2]);
#pragma unroll
            for (int u = 0; u < 8; ++u) {
                float kv = KPs[m * PAD + tk + 16 * u];
                unsigned long long kv2 = pack2(kv, kv);
#pragma unroll
                for (int i2 = 0; i2 < 4; ++i2) fma2(s2[u][i2], q2[i2], kv2);
            }
        }

        // ---- online softmax (registers + 16-lane shuffles) ----
#pragma unroll
        for (int i2 = 0; i2 < 4; ++i2) {
            float a0 = ninf(), a1 = ninf();
#pragma unroll
            for (int u = 0; u < 8; ++u) {
                float vx, vy; unpack2(s2[u][i2], vx, vy);
                a0 = fmaxf(a0, vx); a1 = fmaxf(a1, vy);
            }
#pragma unroll
            for (int d = 1; d < 16; d <<= 1) {
                a0 = fmaxf(a0, __shfl_xor_sync(0xFFFFFFFFu, a0, d));
                a1 = fmaxf(a1, __shfl_xor_sync(0xFFFFFFFFu, a1, d));
            }
            const int r0 = 2 * i2, r1 = r0 + 1;
            float mn0 = fmaxf(mrow[r0], a0);
            float mn1 = fmaxf(mrow[r1], a1);
            float sc0 = __expf(mrow[r0] - mn0);
            float sc1 = __expf(mrow[r1] - mn1);
            mrow[r0] = mn0; mrow[r1] = mn1;
            float su0 = 0.f, su1 = 0.f;
#pragma unroll
            for (int u = 0; u < 8; ++u) {
                float vx, vy; unpack2(s2[u][i2], vx, vy);
                vx = __expf(vx - mn0);
                vy = __expf(vy - mn1);
                su0 += vx; su1 += vy;
                s2[u][i2] = pack2(vx, vy);
            }
#pragma unroll
            for (int d = 1; d < 16; d <<= 1) {
                su0 += __shfl_xor_sync(0xFFFFFFFFu, su0, d);
                su1 += __shfl_xor_sync(0xFFFFFFFFu, su1, d);
            }
            lrow[r0] = lrow[r0] * sc0 + su0;
            lrow[r1] = lrow[r1] * sc1 + su1;
            unsigned long long scp = pack2(sc0, sc1);
#pragma unroll
            for (int u = 0; u < 8; ++u) mul2(o2[u][i2], scp);
        }

        __syncthreads();  // everyone done reading Ks
        // P -> KPs as [k][q] (packed q-pair stores, 8B aligned since PAD even)
#pragma unroll
        for (int u = 0; u < 8; ++u) {
            int k = tk + 16 * u;
#pragma unroll
            for (int i2 = 0; i2 < 4; ++i2)
                *reinterpret_cast<unsigned long long*>(&KPs[k * PAD + tq * 8 + 2 * i2]) = s2[u][i2];
        }
        __syncthreads();

        // ---- O += P @ V ----
#pragma unroll 4
        for (int k = 0; k < 128; ++k) {
            unsigned long long p2[4];
#pragma unroll
            for (int i2 = 0; i2 < 4; ++i2)
                p2[i2] = lds2(&KPs[k * PAD + tq * 8 + 2 * i2]);
#pragma unroll
            for (int u = 0; u < 8; ++u) {
                float vv = Vs[k * PAD + tk + 16 * u];
                unsigned long long vv2 = pack2(vv, vv);
#pragma unroll
                for (int i2 = 0; i2 < 4; ++i2) fma2(o2[u][i2], p2[i2], vv2);
            }
        }
    }

    // ---- dump partial O (unnormalized) + (m, l) ----
    __syncthreads();
#pragma unroll
    for (int u = 0; u < 8; ++u) {
        int m = tk + 16 * u;
#pragma unroll
        for (int i2 = 0; i2 < 4; ++i2) {
            float vx, vy; unpack2(o2[u][i2], vx, vy);
            int q = tq * 8 + 2 * i2;
            KPs[q * 128 + m]       = vx;   // raw [q][m], reuse buffer
            KPs[(q + 1) * 128 + m] = vy;
        }
    }
    __syncthreads();
    const int obase = ((sp * BB + b) * NT + qt) << 14;
    for (int idx = t; idx < 128 * 128; idx += 256) g_Op[obase + idx] = KPs[idx];
    if (tk == 0) {
        const int mb = ((sp * BB + b) * NT + qt) * 256;
#pragma unroll
        for (int i = 0; i < 8; ++i) {
            g_ml[mb + tq * 8 + i]       = mrow[i];
            g_ml[mb + 128 + tq * 8 + i] = lrow[i];
        }
    }
}

// ============================================================================
// Phase 3: merge splits + w4 epilogue + bias + residual. grid (NT, B), 256 thr.
// smem: Os[m][q] pad 130 | w4s[m][c] pad 258 | ws[3][128] | invl[128]
// ============================================================================
#define OS_OFF   0
#define W4_OFF   (128 * 130)
#define WS_OFF   (W4_OFF + 128 * 258)
#define INVL_OFF (WS_OFF + 3 * 128)
#define COMB_FLOATS (INVL_OFF + 128)

__global__ void __launch_bounds__(256, 1) combine_kernel(
    const float* __restrict__ x, const float* __restrict__ w4,
    const float* __restrict__ b4, float* __restrict__ out)
{
    extern __shared__ float sm[];
    float* Os   = sm + OS_OFF;
    float* w4s  = sm + W4_OFF;
    float* ws   = sm + WS_OFF;
    float* invl = sm + INVL_OFF;

    const int qt = blockIdx.x;
    const int b  = blockIdx.y;
    const int t  = threadIdx.x;

    if (t < 128) {
        float m0 = ninf(); float msv[SPLITS], lsv[SPLITS];
#pragma unroll
        for (int s = 0; s < SPLITS; ++s) {
            const int mb = ((s * BB + b) * NT + qt) * 256;
            msv[s] = g_ml[mb + t];
            lsv[s] = g_ml[mb + 128 + t];
            m0 = fmaxf(m0, msv[s]);
        }
        float lsum = 0.f;
#pragma unroll
        for (int s = 0; s < SPLITS; ++s) {
            float w = __expf(msv[s] - m0);
            ws[s * 128 + t] = w;
            lsum += lsv[s] * w;
        }
        invl[t] = 1.f / lsum;
    }
    // w4s[m][c] (transpose of w4 [c][m])
    for (int idx = t; idx < CC * MID; idx += 256) {
        int c = idx >> 7, m = idx & 127;
        w4s[m * 258 + c] = w4[idx];
    }
    __syncthreads();

    // merge partials into Os[m][q], normalized
    for (int idx = t; idx < 128 * 128; idx += 256) {
        int q = idx >> 7, m = idx & 127;
        float a = 0.f;
#pragma unroll
        for (int s = 0; s < SPLITS; ++s) {
            const int ob = ((s * BB + b) * NT + qt) << 14;
            a += g_Op[ob + idx] * ws[s * 128 + q];
        }
        Os[m * PAD + q] = a * invl[q];
    }
    __syncthreads();

    // epilogue GEMM: e[c][q] = sum_m w4s[m][c] * Os[m][q]
    const int tc = t >> 4;   // 16 c-groups (16 c each, paired)
    const int tn = t & 15;   // lane side = q (coalesced out)
    unsigned long long e2[8][8];
#pragma unroll
    for (int v = 0; v < 8; ++v)
#pragma unroll
        for (int u = 0; u < 8; ++u) e2[v][u] = 0ULL;

#pragma unroll 4
    for (int m = 0; m < 128; ++m) {
        unsigned long long wv[8];
#pragma unroll
        for (int v = 0; v < 8; ++v)
            wv[v] = lds2(&w4s[m * 258 + tc * 16 + 2 * v]);
#pragma unroll
        for (int u = 0; u < 8; ++u) {
            float ov = Os[m * PAD + tn + 16 * u];
            unsigned long long ov2 = pack2(ov, ov);
#pragma unroll
            for (int v = 0; v < 8; ++v) fma2(e2[v][u], wv[v], ov2);
        }
    }

    const int n0 = qt * 128;
#pragma unroll
    for (int v = 0; v < 8; ++v) {
        int c = tc * 16 + 2 * v;
        float bv0 = b4[c], bv1 = b4[c + 1];
#pragma unroll
        for (int u = 0; u < 8; ++u) {
            float ex, ey; unpack2(e2[v][u], ex, ey);
            int q = tn + 16 * u;
            int i0 = (b * CC + c) * NN + n0 + q;
            int i1 = i0 + NN;
            out[i0] = x[i0] + bv0 + ex;
            out[i1] = x[i1] + bv1 + ey;
        }
    }
}

// ============================================================================
extern "C" void kernel_launch(void* const* d_in, const int* in_sizes, int n_in,
                              void* d_out, int out_size)
{
    (void)in_sizes; (void)n_in; (void)out_size;
    const float* x  = (const float*)d_in[0];
    const float* w1 = (const float*)d_in[1];
    const float* b1 = (const float*)d_in[2];
    const float* w2 = (const float*)d_in[3];
    const float* b2 = (const float*)d_in[4];
    const float* w3 = (const float*)d_in[5];
    const float* b3 = (const float*)d_in[6];
    const float* w4 = (const float*)d_in[7];
    const float* b4 = (const float*)d_in[8];
    float* out = (float*)d_out;

    const int attn_smem = 3 * 128 * PAD * (int)sizeof(float);     // 199,680 B
    const int comb_smem = COMB_FLOATS * (int)sizeof(float);       // 200,704 B
    cudaFuncSetAttribute(attn_kernel, cudaFuncAttributeMaxDynamicSharedMemorySize, attn_smem);
    cudaFuncSetAttribute(combine_kernel, cudaFuncAttributeMaxDynamicSharedMemorySize, comb_smem);

    proj_kernel<<<dim3(NT, 12, BB), 64>>>(x, w1, b1, w2, b2, w3, b3);
    attn_kernel<<<dim3(NT, BB, SPLITS), 256, attn_smem>>>();
    combine_kernel<<<dim3(NT, BB), 256, comb_smem>>>(x, w4, b4, out);
}

// round 14
// speedup vs baseline: 1.0453x; 1.0453x over previous
#include <cuda_runtime.h>

#define BB 2
#define CC 256
#define MID 128
#define NN 6272
#define NT 49
#define SPLITS 3
#define PAD 130

// -------- static scratch (no runtime allocation allowed) --------
__device__ float g_Q[BB * MID * NN];
__device__ float g_K[BB * MID * NN];
__device__ float g_V[BB * MID * NN];
__device__ float g_Op[SPLITS * BB * NT * 128 * 128];   // partial O, [s][b][qt][q][m]
__device__ float g_ml[SPLITS * BB * NT * 256];          // per row: [0..127]=m, [128..255]=l

// -------- packed f32x2 helpers (PTX-only; ptxas never auto-fuses) --------
__device__ __forceinline__ unsigned long long pack2(float lo, float hi) {
    unsigned long long r;
    asm("mov.b64 %0, {%1, %2};" : "=l"(r) : "f"(lo), "f"(hi));
    return r;
}
__device__ __forceinline__ void unpack2(unsigned long long v, float& lo, float& hi) {
    asm("mov.b64 {%0, %1}, %2;" : "=f"(lo), "=f"(hi) : "l"(v));
}
__device__ __forceinline__ void fma2(unsigned long long& d, unsigned long long a, unsigned long long b) {
    asm("fma.rn.f32x2 %0, %1, %2, %0;" : "+l"(d) : "l"(a), "l"(b));
}
__device__ __forceinline__ void mul2(unsigned long long& d, unsigned long long a) {
    asm("mul.rn.f32x2 %0, %0, %1;" : "+l"(d) : "l"(a));
}
__device__ __forceinline__ unsigned long long lds2(const float* p) {
    return *reinterpret_cast<const unsigned long long*>(p);
}
__device__ __forceinline__ float ninf() { return __int_as_float(0xff800000); }

// ============================================================================
// Phase 1: QKV projection. out[b][m][n] = bias[m] + sum_c w[m][c]*x[b][c][n]
// grid (49 ntiles, 12 mchunks-of-32 over 384, B), block 64 (2 n per thread)
// ============================================================================
__global__ void __launch_bounds__(64) proj_kernel(
    const float* __restrict__ x,
    const float* __restrict__ w1, const float* __restrict__ b1,
    const float* __restrict__ w2, const float* __restrict__ b2,
    const float* __restrict__ w3, const float* __restrict__ b3)
{
    __shared__ float wsm[CC][34];  // [c][j], pad 34 keeps 8B alignment + low conflicts
    const int nt = blockIdx.x;
    const int mg = blockIdx.y;
    const int b  = blockIdx.z;
    const int t  = threadIdx.x;

    const int mbase  = (mg & 3) * 32;
    const int which  = mg >> 2;
    const float* w   = (which == 0) ? w1 : ((which == 1) ? w2 : w3);
    const float* bb  = (which == 0) ? b1 : ((which == 1) ? b2 : b3);
    float* out       = (which == 0) ? g_Q : ((which == 1) ? g_K : g_V);

    for (int idx = t; idx < 32 * CC; idx += 64) {
        int j = idx >> 8;
        int c = idx & 255;
        wsm[c][j] = w[(mbase + j) * CC + c];
    }
    __syncthreads();

    const int n0 = nt * 128 + 2 * t;
    const float* xp = x + (b * CC) * NN + n0;

    unsigned long long acc0[16], acc1[16];
#pragma unroll
    for (int j = 0; j < 16; ++j) { acc0[j] = 0ULL; acc1[j] = 0ULL; }

#pragma unroll 4
    for (int c = 0; c < CC; ++c) {
        float2 xv = *reinterpret_cast<const float2*>(xp + c * NN);
        unsigned long long xa = pack2(xv.x, xv.x);
        unsigned long long xb = pack2(xv.y, xv.y);
#pragma unroll
        for (int j = 0; j < 16; ++j) {
            unsigned long long wv = lds2(&wsm[c][2 * j]);
            fma2(acc0[j], xa, wv);
            fma2(acc1[j], xb, wv);
        }
    }

#pragma unroll
    for (int j = 0; j < 16; ++j) {
        float a0, a1, c0, c1;
        unpack2(acc0[j], a0, a1);
        unpack2(acc1[j], c0, c1);
        int m0 = mbase + 2 * j;
        float bv0 = bb[m0], bv1 = bb[m0 + 1];
        int base0 = (b * MID + m0) * NN + n0;
        int base1 = (b * MID + m0 + 1) * NN + n0;
        out[base0]     = a0 + bv0;
        out[base0 + 1] = c0 + bv0;
        out[base1]     = a1 + bv1;
        out[base1 + 1] = c1 + bv1;
    }
}

// ============================================================================
// Phase 2: flash attention, split-K=3. grid (NT, B, SPLITS), 256 threads.
// smem: Qs[m][q] | KPs (K[m][k] then P[k][q]) | Vs[k][m], all rows padded to 130.
// Thread (tq=t>>4, tk=t&15): q rows tq*8..+7 (paired for f32x2), k/m cols tk+16u.
// ============================================================================
__global__ void __launch_bounds__(256, 1) attn_kernel()
{
    extern __shared__ float sm[];
    float* Qs  = sm;
    float* KPs = sm + 128 * PAD;
    float* Vs  = sm + 2 * 128 * PAD;

    const int qt = blockIdx.x;
    const int b  = blockIdx.y;
    const int sp = blockIdx.z;
    const int t  = threadIdx.x;
    const int tq = t >> 4;
    const int tk = t & 15;
    const int q0 = qt * 128;

    const float* Qb = g_Q + b * MID * NN;
    const float* Kb = g_K + b * MID * NN;
    const float* Vb = g_V + b * MID * NN;

    // Q tile: Qs[m][q]
    for (int idx = t; idx < 128 * 128; idx += 256) {
        int m = idx >> 7, q = idx & 127;
        Qs[m * PAD + q] = Qb[m * NN + q0 + q];
    }

    unsigned long long o2[8][4];
#pragma unroll
    for (int u = 0; u < 8; ++u)
#pragma unroll
        for (int i2 = 0; i2 < 4; ++i2) o2[u][i2] = 0ULL;
    float mrow[8], lrow[8];
#pragma unroll
    for (int i = 0; i < 8; ++i) { mrow[i] = ninf(); lrow[i] = 0.f; }

    const int kt0 = sp * 16 + (sp > 0 ? 1 : 0);
    const int kt1 = kt0 + (sp == 0 ? 17 : 16);

    for (int kt = kt0; kt < kt1; ++kt) {
        __syncthreads();  // protect KPs/Vs from previous-iter readers
        const int k0g = kt * 128;
        for (int idx = t; idx < 128 * 128; idx += 256) {
            int m = idx >> 7, k = idx & 127;
            KPs[m * PAD + k] = Kb[m * NN + k0g + k];
        }
        for (int idx = t; idx < 128 * 128; idx += 256) {
            int m = idx >> 7, k = idx & 127;
            Vs[k * PAD + m] = Vb[m * NN + k0g + k];  // transpose to [k][m]
        }
        __syncthreads();

        // ---- S = Q @ K^T ----
        unsigned long long s2[8][4];
#pragma unroll
        for (int u = 0; u < 8; ++u)
#pragma unroll
            for (int i2 = 0; i2 < 4; ++i2) s2[u][i2] = 0ULL;

#pragma unroll 4
        for (int m = 0; m < 128; ++m) {
            unsigned long long q2[4];
#pragma unroll
            for (int i2 = 0; i2 < 4; ++i2)
                q2[i2] = lds2(&Qs[m * PAD + tq * 8 + 2 * i2]);
#pragma unroll
            for (int u = 0; u < 8; ++u) {
                float kv = KPs[m * PAD + tk + 16 * u];
                unsigned long long kv2 = pack2(kv, kv);
#pragma unroll
                for (int i2 = 0; i2 < 4; ++i2) fma2(s2[u][i2], q2[i2], kv2);
            }
        }

        // ---- online softmax (registers + 16-lane shuffles) ----
#pragma unroll
        for (int i2 = 0; i2 < 4; ++i2) {
            float a0 = ninf(), a1 = ninf();
#pragma unroll
            for (int u = 0; u < 8; ++u) {
                float vx, vy; unpack2(s2[u][i2], vx, vy);
                a0 = fmaxf(a0, vx); a1 = fmaxf(a1, vy);
            }
#pragma unroll
            for (int d = 1; d < 16; d <<= 1) {
                a0 = fmaxf(a0, __shfl_xor_sync(0xFFFFFFFFu, a0, d));
                a1 = fmaxf(a1, __shfl_xor_sync(0xFFFFFFFFu, a1, d));
            }
            const int r0 = 2 * i2, r1 = r0 + 1;
            float mn0 = fmaxf(mrow[r0], a0);
            float mn1 = fmaxf(mrow[r1], a1);
            float sc0 = __expf(mrow[r0] - mn0);
            float sc1 = __expf(mrow[r1] - mn1);
            mrow[r0] = mn0; mrow[r1] = mn1;
            float su0 = 0.f, su1 = 0.f;
#pragma unroll
            for (int u = 0; u < 8; ++u) {
                float vx, vy; unpack2(s2[u][i2], vx, vy);
                vx = __expf(vx - mn0);
                vy = __expf(vy - mn1);
                su0 += vx; su1 += vy;
                s2[u][i2] = pack2(vx, vy);
            }
#pragma unroll
            for (int d = 1; d < 16; d <<= 1) {
                su0 += __shfl_xor_sync(0xFFFFFFFFu, su0, d);
                su1 += __shfl_xor_sync(0xFFFFFFFFu, su1, d);
            }
            lrow[r0] = lrow[r0] * sc0 + su0;
            lrow[r1] = lrow[r1] * sc1 + su1;
            unsigned long long scp = pack2(sc0, sc1);
#pragma unroll
            for (int u = 0; u < 8; ++u) mul2(o2[u][i2], scp);
        }

        __syncthreads();  // everyone done reading Ks
        // P -> KPs as [k][q] (packed q-pair stores, 8B aligned since PAD even)
#pragma unroll
        for (int u = 0; u < 8; ++u) {
            int k = tk + 16 * u;
#pragma unroll
            for (int i2 = 0; i2 < 4; ++i2)
                *reinterpret_cast<unsigned long long*>(&KPs[k * PAD + tq * 8 + 2 * i2]) = s2[u][i2];
        }
        __syncthreads();

        // ---- O += P @ V ----
#pragma unroll 4
        for (int k = 0; k < 128; ++k) {
            unsigned long long p2[4];
#pragma unroll
            for (int i2 = 0; i2 < 4; ++i2)
                p2[i2] = lds2(&KPs[k * PAD + tq * 8 + 2 * i2]);
#pragma unroll
            for (int u = 0; u < 8; ++u) {
                float vv = Vs[k * PAD + tk + 16 * u];
                unsigned long long vv2 = pack2(vv, vv);
#pragma unroll
                for (int i2 = 0; i2 < 4; ++i2) fma2(o2[u][i2], p2[i2], vv2);
            }
        }
    }

    // ---- dump partial O (unnormalized) + (m, l) ----
    __syncthreads();
#pragma unroll
    for (int u = 0; u < 8; ++u) {
        int m = tk + 16 * u;
#pragma unroll
        for (int i2 = 0; i2 < 4; ++i2) {
            float vx, vy; unpack2(o2[u][i2], vx, vy);
            int q = tq * 8 + 2 * i2;
            KPs[q * 128 + m]       = vx;   // raw [q][m], reuse buffer
            KPs[(q + 1) * 128 + m] = vy;
        }
    }
    __syncthreads();
    const int obase = ((sp * BB + b) * NT + qt) << 14;
    for (int idx = t; idx < 128 * 128; idx += 256) g_Op[obase + idx] = KPs[idx];
    if (tk == 0) {
        const int mb = ((sp * BB + b) * NT + qt) * 256;
#pragma unroll
        for (int i = 0; i < 8; ++i) {
            g_ml[mb + tq * 8 + i]       = mrow[i];
            g_ml[mb + 128 + tq * 8 + i] = lrow[i];
        }
    }
}

// ============================================================================
// Phase 3: merge splits + w4 epilogue + bias + residual. grid (NT, B), 256 thr.
// smem: Os[m][q] pad 130 | w4s[m][c] pad 258 | ws[3][128] | invl[128]
// ============================================================================
#define OS_OFF   0
#define W4_OFF   (128 * 130)
#define WS_OFF   (W4_OFF + 128 * 258)
#define INVL_OFF (WS_OFF + 3 * 128)
#define COMB_FLOATS (INVL_OFF + 128)

__global__ void __launch_bounds__(256, 1) combine_kernel(
    const float* __restrict__ x, const float* __restrict__ w4,
    const float* __restrict__ b4, float* __restrict__ out)
{
    extern __shared__ float sm[];
    float* Os   = sm + OS_OFF;
    float* w4s  = sm + W4_OFF;
    float* ws   = sm + WS_OFF;
    float* invl = sm + INVL_OFF;

    const int qt = blockIdx.x;
    const int b  = blockIdx.y;
    const int t  = threadIdx.x;

    if (t < 128) {
        float m0 = ninf(); float msv[SPLITS], lsv[SPLITS];
#pragma unroll
        for (int s = 0; s < SPLITS; ++s) {
            const int mb = ((s * BB + b) * NT + qt) * 256;
            msv[s] = g_ml[mb + t];
            lsv[s] = g_ml[mb + 128 + t];
            m0 = fmaxf(m0, msv[s]);
        }
        float lsum = 0.f;
#pragma unroll
        for (int s = 0; s < SPLITS; ++s) {
            float w = __expf(msv[s] - m0);
            ws[s * 128 + t] = w;
            lsum += lsv[s] * w;
        }
        invl[t] = 1.f / lsum;
    }
    // w4s[m][c] (transpose of w4 [c][m])
    for (int idx = t; idx < CC * MID; idx += 256) {
        int c = idx >> 7, m = idx & 127;
        w4s[m * 258 + c] = w4[idx];
    }
    __syncthreads();

    // merge partials into Os[m][q], normalized
    for (int idx = t; idx < 128 * 128; idx += 256) {
        int q = idx >> 7, m = idx & 127;
        float a = 0.f;
#pragma unroll
        for (int s = 0; s < SPLITS; ++s) {
            const int ob = ((s * BB + b) * NT + qt) << 14;
            a += g_Op[ob + idx] * ws[s * 128 + q];
        }
        Os[m * PAD + q] = a * invl[q];
    }
    __syncthreads();

    // epilogue GEMM: e[c][q] = sum_m w4s[m][c] * Os[m][q]
    const int tc = t >> 4;   // 16 c-groups (16 c each, paired)
    const int tn = t & 15;   // lane side = q (coalesced out)
    unsigned long long e2[8][8];
#pragma unroll
    for (int v = 0; v < 8; ++v)
#pragma unroll
        for (int u = 0; u < 8; ++u) e2[v][u] = 0ULL;

#pragma unroll 4
    for (int m = 0; m < 128; ++m) {
        unsigned long long wv[8];
#pragma unroll
        for (int v = 0; v < 8; ++v)
            wv[v] = lds2(&w4s[m * 258 + tc * 16 + 2 * v]);
#pragma unroll
        for (int u = 0; u < 8; ++u) {
            float ov = Os[m * PAD + tn + 16 * u];
            unsigned long long ov2 = pack2(ov, ov);
#pragma unroll
            for (int v = 0; v < 8; ++v) fma2(e2[v][u], wv[v], ov2);
        }
    }

    const int n0 = qt * 128;
#pragma unroll
    for (int v = 0; v < 8; ++v) {
        int c = tc * 16 + 2 * v;
        float bv0 = b4[c], bv1 = b4[c + 1];
#pragma unroll
        for (int u = 0; u < 8; ++u) {
            float ex, ey; unpack2(e2[v][u], ex, ey);
            int q = tn + 16 * u;
            int i0 = (b * CC + c) * NN + n0 + q;
            int i1 = i0 + NN;
            out[i0] = x[i0] + bv0 + ex;
            out[i1] = x[i1] + bv1 + ey;
        }
    }
}

// ============================================================================
extern "C" void kernel_launch(void* const* d_in, const int* in_sizes, int n_in,
                              void* d_out, int out_size)
{
    (void)in_sizes; (void)n_in; (void)out_size;
    const float* x  = (const float*)d_in[0];
    const float* w1 = (const float*)d_in[1];
    const float* b1 = (const float*)d_in[2];
    const float* w2 = (const float*)d_in[3];
    const float* b2 = (const float*)d_in[4];
    const float* w3 = (const float*)d_in[5];
    const float* b3 = (const float*)d_in[6];
    const float* w4 = (const float*)d_in[7];
    const float* b4 = (const float*)d_in[8];
    float* out = (float*)d_out;

    const int attn_smem = 3 * 128 * PAD * (int)sizeof(float);     // 199,680 B
    const int comb_smem = COMB_FLOATS * (int)sizeof(float);       // 200,704 B
    cudaFuncSetAttribute(attn_kernel, cudaFuncAttributeMaxDynamicSharedMemorySize, attn_smem);
    cudaFuncSetAttribute(combine_kernel, cudaFuncAttributeMaxDynamicSharedMemorySize, comb_smem);

    proj_kernel<<<dim3(NT, 12, BB), 64>>>(x, w1, b1, w2, b2, w3, b3);
    attn_kernel<<<dim3(NT, BB, SPLITS), 256, attn_smem>>>();
    combine_kernel<<<dim3(NT, BB), 256, comb_smem>>>(x, w4, b4, out);
}

// round 15
// speedup vs baseline: 1.2489x; 1.1948x over previous
#include <cuda_runtime.h>

#define BB 2
#define CC 256
#define MID 128
#define NN 6272
#define NT 49
#define SPLITS 3
#define PAD 130

// -------- static scratch (no runtime allocation allowed) --------
__device__ float g_Q[BB * MID * NN];
__device__ float g_K[BB * MID * NN];
__device__ float g_V[BB * MID * NN];
__device__ float g_Op[SPLITS * BB * NT * 128 * 128];   // partial O, [s][b][qt][q][m]
__device__ float g_ml[SPLITS * BB * NT * 256];          // per row: [0..127]=m, [128..255]=l

// -------- packed f32x2 helpers (PTX-only; ptxas never auto-fuses) --------
__device__ __forceinline__ unsigned long long pack2(float lo, float hi) {
    unsigned long long r;
    asm("mov.b64 %0, {%1, %2};" : "=l"(r) : "f"(lo), "f"(hi));
    return r;
}
__device__ __forceinline__ void unpack2(unsigned long long v, float& lo, float& hi) {
    asm("mov.b64 {%0, %1}, %2;" : "=f"(lo), "=f"(hi) : "l"(v));
}
__device__ __forceinline__ void fma2(unsigned long long& d, unsigned long long a, unsigned long long b) {
    asm("fma.rn.f32x2 %0, %1, %2, %0;" : "+l"(d) : "l"(a), "l"(b));
}
__device__ __forceinline__ void mul2(unsigned long long& d, unsigned long long a) {
    asm("mul.rn.f32x2 %0, %0, %1;" : "+l"(d) : "l"(a));
}
__device__ __forceinline__ unsigned long long lds2(const float* p) {
    return *reinterpret_cast<const unsigned long long*>(p);
}
__device__ __forceinline__ float ninf() { return __int_as_float(0xff800000); }

// ============================================================================
// Phase 1: QKV projection. out[b][m][n] = bias[m] + sum_c w[m][c]*x[b][c][n]
// grid (49 ntiles, 12 mchunks-of-32 over 384, B), block 64 (2 n per thread)
// ============================================================================
__global__ void __launch_bounds__(64) proj_kernel(
    const float* __restrict__ x,
    const float* __restrict__ w1, const float* __restrict__ b1,
    const float* __restrict__ w2, const float* __restrict__ b2,
    const float* __restrict__ w3, const float* __restrict__ b3)
{
    __shared__ float wsm[CC][34];  // [c][j], pad 34 keeps 8B alignment + low conflicts
    const int nt = blockIdx.x;
    const int mg = blockIdx.y;
    const int b  = blockIdx.z;
    const int t  = threadIdx.x;

    const int mbase  = (mg & 3) * 32;
    const int which  = mg >> 2;
    const float* w   = (which == 0) ? w1 : ((which == 1) ? w2 : w3);
    const float* bb  = (which == 0) ? b1 : ((which == 1) ? b2 : b3);
    float* out       = (which == 0) ? g_Q : ((which == 1) ? g_K : g_V);

    for (int idx = t; idx < 32 * CC; idx += 64) {
        int j = idx >> 8;
        int c = idx & 255;
        wsm[c][j] = w[(mbase + j) * CC + c];
    }
    __syncthreads();

    const int n0 = nt * 128 + 2 * t;
    const float* xp = x + (b * CC) * NN + n0;

    unsigned long long acc0[16], acc1[16];
#pragma unroll
    for (int j = 0; j < 16; ++j) { acc0[j] = 0ULL; acc1[j] = 0ULL; }

#pragma unroll 8
    for (int c = 0; c < CC; ++c) {
        float2 xv = *reinterpret_cast<const float2*>(xp + c * NN);
        unsigned long long xa = pack2(xv.x, xv.x);
        unsigned long long xb = pack2(xv.y, xv.y);
#pragma unroll
        for (int j = 0; j < 16; ++j) {
            unsigned long long wv = lds2(&wsm[c][2 * j]);
            fma2(acc0[j], xa, wv);
            fma2(acc1[j], xb, wv);
        }
    }

#pragma unroll
    for (int j = 0; j < 16; ++j) {
        float a0, a1, c0, c1;
        unpack2(acc0[j], a0, a1);
        unpack2(acc1[j], c0, c1);
        int m0 = mbase + 2 * j;
        float bv0 = bb[m0], bv1 = bb[m0 + 1];
        int base0 = (b * MID + m0) * NN + n0;
        int base1 = (b * MID + m0 + 1) * NN + n0;
        out[base0]     = a0 + bv0;
        out[base0 + 1] = c0 + bv0;
        out[base1]     = a1 + bv1;
        out[base1 + 1] = c1 + bv1;
    }
}

// ============================================================================
// Phase 2: flash attention, split-K=3. grid (NT, B, SPLITS), 256 threads.
// smem: Qs[m][q] | KPs (K[m][k] then P[k][q]) | Vs[m][k] — rows padded to 130.
// V is kept UN-transposed: PV-loop read Vs[(tk+16u)*PAD + k] is conflict-free
// under PAD=130 (lane banks 2*tk distinct; upper half-warp broadcasts), which
// removes the old 16-way-conflicted transpose store entirely.
// All tile loads are float2 (8B-aligned: even smem offset, even gmem offset).
// ============================================================================
__global__ void __launch_bounds__(256, 1) attn_kernel()
{
    extern __shared__ float sm[];
    float* Qs  = sm;
    float* KPs = sm + 128 * PAD;
    float* Vs  = sm + 2 * 128 * PAD;

    const int qt = blockIdx.x;
    const int b  = blockIdx.y;
    const int sp = blockIdx.z;
    const int t  = threadIdx.x;
    const int tq = t >> 4;
    const int tk = t & 15;
    const int q0 = qt * 128;

    const float* Qb = g_Q + b * MID * NN;
    const float* Kb = g_K + b * MID * NN;
    const float* Vb = g_V + b * MID * NN;

    // Q tile: Qs[m][q], float2 vectorized (32 iters of LDG.64 + STS.64)
    for (int idx = t; idx < 8192; idx += 256) {
        int m  = idx >> 6;
        int c2 = (idx & 63) << 1;
        *reinterpret_cast<unsigned long long*>(&Qs[m * PAD + c2]) =
            *reinterpret_cast<const unsigned long long*>(&Qb[m * NN + q0 + c2]);
    }

    unsigned long long o2[8][4];
#pragma unroll
    for (int u = 0; u < 8; ++u)
#pragma unroll
        for (int i2 = 0; i2 < 4; ++i2) o2[u][i2] = 0ULL;
    float mrow[8], lrow[8];
#pragma unroll
    for (int i = 0; i < 8; ++i) { mrow[i] = ninf(); lrow[i] = 0.f; }

    const int kt0 = sp * 16 + (sp > 0 ? 1 : 0);
    const int kt1 = kt0 + (sp == 0 ? 17 : 16);

    for (int kt = kt0; kt < kt1; ++kt) {
        __syncthreads();  // protect KPs/Vs from previous-iter readers (also covers Q load)
        const int k0g = kt * 128;
        // K and V tiles, both [m][k] straight copies, float2 vectorized.
        // Interleaved in one loop for higher MLP.
        for (int idx = t; idx < 8192; idx += 256) {
            int m  = idx >> 6;
            int c2 = (idx & 63) << 1;
            int go = m * NN + k0g + c2;
            int so = m * PAD + c2;
            *reinterpret_cast<unsigned long long*>(&KPs[so]) =
                *reinterpret_cast<const unsigned long long*>(&Kb[go]);
            *reinterpret_cast<unsigned long long*>(&Vs[so]) =
                *reinterpret_cast<const unsigned long long*>(&Vb[go]);
        }
        __syncthreads();

        // ---- S = Q @ K^T ----
        unsigned long long s2[8][4];
#pragma unroll
        for (int u = 0; u < 8; ++u)
#pragma unroll
            for (int i2 = 0; i2 < 4; ++i2) s2[u][i2] = 0ULL;

#pragma unroll 4
        for (int m = 0; m < 128; ++m) {
            unsigned long long q2[4];
#pragma unroll
            for (int i2 = 0; i2 < 4; ++i2)
                q2[i2] = lds2(&Qs[m * PAD + tq * 8 + 2 * i2]);
#pragma unroll
            for (int u = 0; u < 8; ++u) {
                float kv = KPs[m * PAD + tk + 16 * u];
                unsigned long long kv2 = pack2(kv, kv);
#pragma unroll
                for (int i2 = 0; i2 < 4; ++i2) fma2(s2[u][i2], q2[i2], kv2);
            }
        }

        // ---- online softmax (registers + 16-lane shuffles) ----
#pragma unroll
        for (int i2 = 0; i2 < 4; ++i2) {
            float a0 = ninf(), a1 = ninf();
#pragma unroll
            for (int u = 0; u < 8; ++u) {
                float vx, vy; unpack2(s2[u][i2], vx, vy);
                a0 = fmaxf(a0, vx); a1 = fmaxf(a1, vy);
            }
#pragma unroll
            for (int d = 1; d < 16; d <<= 1) {
                a0 = fmaxf(a0, __shfl_xor_sync(0xFFFFFFFFu, a0, d));
                a1 = fmaxf(a1, __shfl_xor_sync(0xFFFFFFFFu, a1, d));
            }
            const int r0 = 2 * i2, r1 = r0 + 1;
            float mn0 = fmaxf(mrow[r0], a0);
            float mn1 = fmaxf(mrow[r1], a1);
            float sc0 = __expf(mrow[r0] - mn0);
            float sc1 = __expf(mrow[r1] - mn1);
            mrow[r0] = mn0; mrow[r1] = mn1;
            float su0 = 0.f, su1 = 0.f;
#pragma unroll
            for (int u = 0; u < 8; ++u) {
                float vx, vy; unpack2(s2[u][i2], vx, vy);
                vx = __expf(vx - mn0);
                vy = __expf(vy - mn1);
                su0 += vx; su1 += vy;
                s2[u][i2] = pack2(vx, vy);
            }
#pragma unroll
            for (int d = 1; d < 16; d <<= 1) {
                su0 += __shfl_xor_sync(0xFFFFFFFFu, su0, d);
                su1 += __shfl_xor_sync(0xFFFFFFFFu, su1, d);
            }
            lrow[r0] = lrow[r0] * sc0 + su0;
            lrow[r1] = lrow[r1] * sc1 + su1;
            unsigned long long scp = pack2(sc0, sc1);
#pragma unroll
            for (int u = 0; u < 8; ++u) mul2(o2[u][i2], scp);
        }

        __syncthreads();  // everyone done reading K
        // P -> KPs as [k][q] (packed q-pair stores, 8B aligned since PAD even)
#pragma unroll
        for (int u = 0; u < 8; ++u) {
            int k = tk + 16 * u;
#pragma unroll
            for (int i2 = 0; i2 < 4; ++i2)
                *reinterpret_cast<unsigned long long*>(&KPs[k * PAD + tq * 8 + 2 * i2]) = s2[u][i2];
        }
        __syncthreads();

        // ---- O += P @ V ----  (V read as Vs[mid][k]; conflict-free, see header)
#pragma unroll 4
        for (int k = 0; k < 128; ++k) {
            unsigned long long p2[4];
#pragma unroll
            for (int i2 = 0; i2 < 4; ++i2)
                p2[i2] = lds2(&KPs[k * PAD + tq * 8 + 2 * i2]);
#pragma unroll
            for (int u = 0; u < 8; ++u) {
                float vv = Vs[(tk + 16 * u) * PAD + k];
                unsigned long long vv2 = pack2(vv, vv);
#pragma unroll
                for (int i2 = 0; i2 < 4; ++i2) fma2(o2[u][i2], p2[i2], vv2);
            }
        }
    }

    // ---- dump partial O (unnormalized) + (m, l) ----
    __syncthreads();
#pragma unroll
    for (int u = 0; u < 8; ++u) {
        int m = tk + 16 * u;
#pragma unroll
        for (int i2 = 0; i2 < 4; ++i2) {
            float vx, vy; unpack2(o2[u][i2], vx, vy);
            int q = tq * 8 + 2 * i2;
            KPs[q * 128 + m]       = vx;   // raw [q][m], reuse buffer
            KPs[(q + 1) * 128 + m] = vy;
        }
    }
    __syncthreads();
    const int obase = ((sp * BB + b) * NT + qt) << 14;
    for (int idx = t; idx < 128 * 128; idx += 256) g_Op[obase + idx] = KPs[idx];
    if (tk == 0) {
        const int mb = ((sp * BB + b) * NT + qt) * 256;
#pragma unroll
        for (int i = 0; i < 8; ++i) {
            g_ml[mb + tq * 8 + i]       = mrow[i];
            g_ml[mb + 128 + tq * 8 + i] = lrow[i];
        }
    }
}

// ============================================================================
// Phase 3: merge splits + w4 epilogue + bias + residual. grid (NT, B), 256 thr.
// smem: Os[m][q] pad 130 | w4s[m][c] pad 258 | ws[3][128] | invl[128]
// ============================================================================
#define OS_OFF   0
#define W4_OFF   (128 * 130)
#define WS_OFF   (W4_OFF + 128 * 258)
#define INVL_OFF (WS_OFF + 3 * 128)
#define COMB_FLOATS (INVL_OFF + 128)

__global__ void __launch_bounds__(256, 1) combine_kernel(
    const float* __restrict__ x, const float* __restrict__ w4,
    const float* __restrict__ b4, float* __restrict__ out)
{
    extern __shared__ float sm[];
    float* Os   = sm + OS_OFF;
    float* w4s  = sm + W4_OFF;
    float* ws   = sm + WS_OFF;
    float* invl = sm + INVL_OFF;

    const int qt = blockIdx.x;
    const int b  = blockIdx.y;
    const int t  = threadIdx.x;

    if (t < 128) {
        float m0 = ninf(); float msv[SPLITS], lsv[SPLITS];
#pragma unroll
        for (int s = 0; s < SPLITS; ++s) {
            const int mb = ((s * BB + b) * NT + qt) * 256;
            msv[s] = g_ml[mb + t];
            lsv[s] = g_ml[mb + 128 + t];
            m0 = fmaxf(m0, msv[s]);
        }
        float lsum = 0.f;
#pragma unroll
        for (int s = 0; s < SPLITS; ++s) {
            float w = __expf(msv[s] - m0);
            ws[s * 128 + t] = w;
            lsum += lsv[s] * w;
        }
        invl[t] = 1.f / lsum;
    }
    // w4s[m][c] (transpose of w4 [c][m])
    for (int idx = t; idx < CC * MID; idx += 256) {
        int c = idx >> 7, m = idx & 127;
        w4s[m * 258 + c] = w4[idx];
    }
    __syncthreads();

    // merge partials into Os[m][q], normalized
    for (int idx = t; idx < 128 * 128; idx += 256) {
        int q = idx >> 7, m = idx & 127;
        float a = 0.f;
#pragma unroll
        for (int s = 0; s < SPLITS; ++s) {
            const int ob = ((s * BB + b) * NT + qt) << 14;
            a += g_Op[ob + idx] * ws[s * 128 + q];
        }
        Os[m * PAD + q] = a * invl[q];
    }
    __syncthreads();

    // epilogue GEMM: e[c][q] = sum_m w4s[m][c] * Os[m][q]
    const int tc = t >> 4;   // 16 c-groups (16 c each, paired)
    const int tn = t & 15;   // lane side = q (coalesced out)
    unsigned long long e2[8][8];
#pragma unroll
    for (int v = 0; v < 8; ++v)
#pragma unroll
        for (int u = 0; u < 8; ++u) e2[v][u] = 0ULL;

#pragma unroll 4
    for (int m = 0; m < 128; ++m) {
        unsigned long long wv[8];
#pragma unroll
        for (int v = 0; v < 8; ++v)
            wv[v] = lds2(&w4s[m * 258 + tc * 16 + 2 * v]);
#pragma unroll
        for (int u = 0; u < 8; ++u) {
            float ov = Os[m * PAD + tn + 16 * u];
            unsigned long long ov2 = pack2(ov, ov);
#pragma unroll
            for (int v = 0; v < 8; ++v) fma2(e2[v][u], wv[v], ov2);
        }
    }

    const int n0 = qt * 128;
#pragma unroll
    for (int v = 0; v < 8; ++v) {
        int c = tc * 16 + 2 * v;
        float bv0 = b4[c], bv1 = b4[c + 1];
#pragma unroll
        for (int u = 0; u < 8; ++u) {
            float ex, ey; unpack2(e2[v][u], ex, ey);
            int q = tn + 16 * u;
            int i0 = (b * CC + c) * NN + n0 + q;
            int i1 = i0 + NN;
            out[i0] = x[i0] + bv0 + ex;
            out[i1] = x[i1] + bv1 + ey;
        }
    }
}

// ============================================================================
extern "C" void kernel_launch(void* const* d_in, const int* in_sizes, int n_in,
                              void* d_out, int out_size)
{
    (void)in_sizes; (void)n_in; (void)out_size;
    const float* x  = (const float*)d_in[0];
    const float* w1 = (const float*)d_in[1];
    const float* b1 = (const float*)d_in[2];
    const float* w2 = (const float*)d_in[3];
    const float* b2 = (const float*)d_in[4];
    const float* w3 = (const float*)d_in[5];
    const float* b3 = (const float*)d_in[6];
    const float* w4 = (const float*)d_in[7];
    const float* b4 = (const float*)d_in[8];
    float* out = (float*)d_out;

    const int attn_smem = 3 * 128 * PAD * (int)sizeof(float);     // 199,680 B
    const int comb_smem = COMB_FLOATS * (int)sizeof(float);       // 200,704 B
    cudaFuncSetAttribute(attn_kernel, cudaFuncAttributeMaxDynamicSharedMemorySize, attn_smem);
    cudaFuncSetAttribute(combine_kernel, cudaFuncAttributeMaxDynamicSharedMemorySize, comb_smem);

    proj_kernel<<<dim3(NT, 12, BB), 64>>>(x, w1, b1, w2, b2, w3, b3);
    attn_kernel<<<dim3(NT, BB, SPLITS), 256, attn_smem>>>();
    combine_kernel<<<dim3(NT, BB), 256, comb_smem>>>(x, w4, b4, out);
}

// round 17
// speedup vs baseline: 2.1954x; 1.7579x over previous
#include <cuda_runtime.h>
#include <cstdint>

#define BB 2
#define CC 256
#define MID 128
#define NN 6272
#define NT 49
#define SPLITS 3

// -------- static scratch (no runtime allocation allowed) --------
__device__ float g_Qt[BB * NN * MID];                  // Q transposed [b][n][mid]
__device__ float g_Kt[BB * NN * MID];                  // K transposed [b][n][mid]
__device__ float g_V [BB * MID * NN];                  // V [b][mid][n]
__device__ float g_Op[SPLITS * BB * NT * 128 * 128];   // partial O, [s][b][qt][q][m]
__device__ float g_ml[SPLITS * BB * NT * 256];         // per row: [0..127]=m, [128..255]=l

// -------- packed f32x2 helpers (proj/combine) --------
__device__ __forceinline__ unsigned long long pack2(float lo, float hi) {
    unsigned long long r;
    asm("mov.b64 %0, {%1, %2};" : "=l"(r) : "f"(lo), "f"(hi));
    return r;
}
__device__ __forceinline__ void unpack2(unsigned long long v, float& lo, float& hi) {
    asm("mov.b64 {%0, %1}, %2;" : "=f"(lo), "=f"(hi) : "l"(v));
}
__device__ __forceinline__ void fma2(unsigned long long& d, unsigned long long a, unsigned long long b) {
    asm("fma.rn.f32x2 %0, %1, %2, %0;" : "+l"(d) : "l"(a), "l"(b));
}
__device__ __forceinline__ unsigned long long lds2(const float* p) {
    return *reinterpret_cast<const unsigned long long*>(p);
}
__device__ __forceinline__ float ninf() { return __int_as_float(0xff800000); }

// -------- warp-level bf16 mma (baseline PTX, no sm_103a-only features) -----
// D(16x8,f32) += A(16x16 row-major bf16) * B(16x8 "col" = B[n][k] rows, bf16)
__device__ __forceinline__ void mma_bf16(float* c, const uint32_t* a,
                                         uint32_t b0, uint32_t b1) {
    asm volatile(
        "mma.sync.aligned.m16n8k16.row.col.f32.bf16.bf16.f32 "
        "{%0,%1,%2,%3}, {%4,%5,%6,%7}, {%8,%9}, {%0,%1,%2,%3};"
        : "+f"(c[0]), "+f"(c[1]), "+f"(c[2]), "+f"(c[3])
        : "r"(a[0]), "r"(a[1]), "r"(a[2]), "r"(a[3]), "r"(b0), "r"(b1));
}

// Load a 128x128 fp32 tile (row stride gstride) into split-bf16 hi/lo smem
// tiles laid out [r][c] with row stride 136 bf16 (272 B) — conflict-free for
// both the STS here and the fragment LDS pattern (banks 4*(lane>>2)+(lane&3)).
__device__ __forceinline__ void load_split_tile(
    const float* __restrict__ g, int gstride, char* sh, char* sl, int t)
{
#pragma unroll 4
    for (int idx = t; idx < 8192; idx += 256) {
        int r = idx >> 6, j = idx & 63;  // pair j -> cols 2j, 2j+1
        float2 v = *reinterpret_cast<const float2*>(g + (size_t)r * gstride + 2 * j);
        uint32_t h2; asm("cvt.rn.bf16x2.f32 %0, %1, %2;" : "=r"(h2) : "f"(v.y), "f"(v.x));
        float hx = __uint_as_float(h2 << 16);
        float hy = __uint_as_float(h2 & 0xffff0000u);
        uint32_t l2; asm("cvt.rn.bf16x2.f32 %0, %1, %2;" : "=r"(l2) : "f"(v.y - hy), "f"(v.x - hx));
        int off = r * 272 + j * 4;
        *reinterpret_cast<uint32_t*>(sh + off) = h2;
        *reinterpret_cast<uint32_t*>(sl + off) = l2;
    }
}

// ============================================================================
// Phase 1: QKV projection. Q,K stored transposed [n][mid]; V stored [mid][n].
// ============================================================================
__global__ void __launch_bounds__(64) proj_kernel(
    const float* __restrict__ x,
    const float* __restrict__ w1, const float* __restrict__ b1,
    const float* __restrict__ w2, const float* __restrict__ b2,
    const float* __restrict__ w3, const float* __restrict__ b3)
{
    __shared__ float wsm[CC][34];
    const int nt = blockIdx.x;
    const int mg = blockIdx.y;
    const int b  = blockIdx.z;
    const int t  = threadIdx.x;

    const int mbase  = (mg & 3) * 32;
    const int which  = mg >> 2;
    const float* w   = (which == 0) ? w1 : ((which == 1) ? w2 : w3);
    const float* bb  = (which == 0) ? b1 : ((which == 1) ? b2 : b3);
    float* out       = (which == 0) ? g_Qt : ((which == 1) ? g_Kt : g_V);

    for (int idx = t; idx < 32 * CC; idx += 64) {
        int j = idx >> 8;
        int c = idx & 255;
        wsm[c][j] = w[(mbase + j) * CC + c];
    }
    __syncthreads();

    const int n0 = nt * 128 + 2 * t;
    const float* xp = x + (size_t)(b * CC) * NN + n0;

    unsigned long long acc0[16], acc1[16];
#pragma unroll
    for (int j = 0; j < 16; ++j) { acc0[j] = 0ULL; acc1[j] = 0ULL; }

#pragma unroll 8
    for (int c = 0; c < CC; ++c) {
        float2 xv = *reinterpret_cast<const float2*>(xp + (size_t)c * NN);
        unsigned long long xa = pack2(xv.x, xv.x);
        unsigned long long xb = pack2(xv.y, xv.y);
#pragma unroll
        for (int j = 0; j < 16; ++j) {
            unsigned long long wv = lds2(&wsm[c][2 * j]);
            fma2(acc0[j], xa, wv);
            fma2(acc1[j], xb, wv);
        }
    }

#pragma unroll
    for (int j = 0; j < 16; ++j) {
        float a0, a1, c0, c1;
        unpack2(acc0[j], a0, a1);
        unpack2(acc1[j], c0, c1);
        int m0 = mbase + 2 * j;
        float bv0 = bb[m0], bv1 = bb[m0 + 1];
        if (which == 2) {
            size_t base0 = (size_t)(b * MID + m0) * NN + n0;
            size_t base1 = (size_t)(b * MID + m0 + 1) * NN + n0;
            out[base0]     = a0 + bv0;
            out[base0 + 1] = c0 + bv0;
            out[base1]     = a1 + bv1;
            out[base1 + 1] = c1 + bv1;
        } else {
            *reinterpret_cast<float2*>(&out[(size_t)(b * NN + n0) * MID + m0]) =
                make_float2(a0 + bv0, a1 + bv1);
            *reinterpret_cast<float2*>(&out[(size_t)(b * NN + n0 + 1) * MID + m0]) =
                make_float2(c0 + bv0, c1 + bv1);
        }
    }
}

// ============================================================================
// Phase 2: mma.sync flash attention, split-K=3, 3-product split-bf16 GEMMs.
// grid (NT, B, SPLITS), 256 threads (8 warps). Warp w owns q rows [16w,16w+16).
// Fragment mapping (PTX m16n8k16): lane g=lane>>2, t=lane&3.
//   A reg0 = A[rA][2t..2t+1], reg1 = A[rA+8][..], reg2/reg3 = +8 cols.
//   B reg0 = Bt[n][2t..2t+1], reg1 = Bt[n][2t+8..]; Bt rows = n (K/V tiles).
//   C c0,c1 = (rA, 2t..2t+1), c2,c3 = (rA+8, ..) per n8 tile.
// P (softmaxed S) is warp-private rows -> written back into the K buffers
// after a block sync, then used as A of PV. V tile = g_V rows (already [m][n]).
// ============================================================================
#define TILE_B 34816                 // 128 rows * 272 B
#define SM_QH  0
#define SM_QL  (1 * TILE_B)
#define SM_KH  (2 * TILE_B)          // K hi, then P hi
#define SM_KL  (3 * TILE_B)          // K lo, then P lo
#define SM_VH  (4 * TILE_B)
#define SM_VL  (5 * TILE_B)
#define ATTN_SMEM (6 * TILE_B)       // 208,896 B

__global__ void __launch_bounds__(256, 1) attn_kernel()
{
    extern __shared__ __align__(16) char sm[];
    char* QH = sm + SM_QH;  char* QL = sm + SM_QL;
    char* KH = sm + SM_KH;  char* KL = sm + SM_KL;
    char* VH = sm + SM_VH;  char* VL = sm + SM_VL;

    const int qt = blockIdx.x, b = blockIdx.y, sp = blockIdx.z;
    const int t = threadIdx.x;
    const int wid = t >> 5, lid = t & 31;
    const int g  = lid >> 2, tt = lid & 3;
    const int rA = wid * 16 + g;         // CTA-local q rows rA and rA+8
    const int q0 = qt * 128;

    // Q tile (persistent)
    load_split_tile(g_Qt + (size_t)(b * NN + q0) * MID, MID, QH, QL, t);

    float oacc[16][4];
#pragma unroll
    for (int n = 0; n < 16; ++n)
#pragma unroll
        for (int j = 0; j < 4; ++j) oacc[n][j] = 0.f;
    float mrA = ninf(), mrB = ninf(), lrA = 0.f, lrB = 0.f;

    const int aoff  = rA * 272 + tt * 4;   // A-frag reg0 byte offset
    const int boffg = g * 272 + tt * 4;    // B-frag base; + n*2176 per n8 tile

    const int kt0 = sp * 16 + (sp > 0 ? 1 : 0);
    const int kt1 = kt0 + (sp == 0 ? 17 : 16);

    for (int kt = kt0; kt < kt1; ++kt) {
        __syncthreads();  // prev PV done reading P(=K buf) and V
        load_split_tile(g_Kt + (size_t)(b * NN + kt * 128) * MID, MID, KH, KL, t);
        load_split_tile(g_V + (size_t)b * MID * NN + kt * 128, NN, VH, VL, t);
        __syncthreads();

        // ---- S = Qh*Kh + Qh*Kl + Ql*Kh ----
        float sacc[16][4];
#pragma unroll
        for (int n = 0; n < 16; ++n)
#pragma unroll
            for (int j = 0; j < 4; ++j) sacc[n][j] = 0.f;

#pragma unroll 2
        for (int ks = 0; ks < 8; ++ks) {
            const int ak = aoff + ks * 32;
            uint32_t ah[4], al[4];
            ah[0] = *reinterpret_cast<uint32_t*>(QH + ak);
            ah[1] = *reinterpret_cast<uint32_t*>(QH + ak + 2176);
            ah[2] = *reinterpret_cast<uint32_t*>(QH + ak + 16);
            ah[3] = *reinterpret_cast<uint32_t*>(QH + ak + 2176 + 16);
            al[0] = *reinterpret_cast<uint32_t*>(QL + ak);
            al[1] = *reinterpret_cast<uint32_t*>(QL + ak + 2176);
            al[2] = *reinterpret_cast<uint32_t*>(QL + ak + 16);
            al[3] = *reinterpret_cast<uint32_t*>(QL + ak + 2176 + 16);
#pragma unroll
            for (int n = 0; n < 16; ++n) {
                const int bk = boffg + n * 2176 + ks * 32;
                uint32_t bh0 = *reinterpret_cast<uint32_t*>(KH + bk);
                uint32_t bh1 = *reinterpret_cast<uint32_t*>(KH + bk + 16);
                uint32_t bl0 = *reinterpret_cast<uint32_t*>(KL + bk);
                uint32_t bl1 = *reinterpret_cast<uint32_t*>(KL + bk + 16);
                mma_bf16(sacc[n], ah, bh0, bh1);
                mma_bf16(sacc[n], ah, bl0, bl1);
                mma_bf16(sacc[n], al, bh0, bh1);
            }
        }

        __syncthreads();  // ALL warps done reading K before P overwrites it

        // ---- online softmax (warp-local: quad shuffles xor 1,2) ----
        float mA = ninf(), mB = ninf();
#pragma unroll
        for (int n = 0; n < 16; ++n) {
            mA = fmaxf(mA, fmaxf(sacc[n][0], sacc[n][1]));
            mB = fmaxf(mB, fmaxf(sacc[n][2], sacc[n][3]));
        }
        mA = fmaxf(mA, __shfl_xor_sync(0xFFFFFFFFu, mA, 1));
        mA = fmaxf(mA, __shfl_xor_sync(0xFFFFFFFFu, mA, 2));
        mB = fmaxf(mB, __shfl_xor_sync(0xFFFFFFFFu, mB, 1));
        mB = fmaxf(mB, __shfl_xor_sync(0xFFFFFFFFu, mB, 2));

        const float mnA = fmaxf(mrA, mA), mnB = fmaxf(mrB, mB);
        const float scA = __expf(mrA - mnA), scB = __expf(mrB - mnB);
        mrA = mnA; mrB = mnB;

        float sumA = 0.f, sumB = 0.f;
        const int poff = rA * 272 + tt * 4;   // P[rA][n*8 + 2t] pair
#pragma unroll
        for (int n = 0; n < 16; ++n) {
            float p0 = __expf(sacc[n][0] - mnA);
            float p1 = __expf(sacc[n][1] - mnA);
            float p2 = __expf(sacc[n][2] - mnB);
            float p3 = __expf(sacc[n][3] - mnB);
            sumA += p0 + p1; sumB += p2 + p3;
            uint32_t h2, l2;
            asm("cvt.rn.bf16x2.f32 %0, %1, %2;" : "=r"(h2) : "f"(p1), "f"(p0));
            {
                float h0 = __uint_as_float(h2 << 16);
                float h1 = __uint_as_float(h2 & 0xffff0000u);
                asm("cvt.rn.bf16x2.f32 %0, %1, %2;" : "=r"(l2) : "f"(p1 - h1), "f"(p0 - h0));
            }
            const int pa = poff + n * 16;
            *reinterpret_cast<uint32_t*>(KH + pa) = h2;
            *reinterpret_cast<uint32_t*>(KL + pa) = l2;
            asm("cvt.rn.bf16x2.f32 %0, %1, %2;" : "=r"(h2) : "f"(p3), "f"(p2));
            {
                float h2f = __uint_as_float(h2 << 16);
                float h3f = __uint_as_float(h2 & 0xffff0000u);
                asm("cvt.rn.bf16x2.f32 %0, %1, %2;" : "=r"(l2) : "f"(p3 - h3f), "f"(p2 - h2f));
            }
            *reinterpret_cast<uint32_t*>(KH + pa + 2176) = h2;
            *reinterpret_cast<uint32_t*>(KL + pa + 2176) = l2;
        }
        sumA += __shfl_xor_sync(0xFFFFFFFFu, sumA, 1);
        sumA += __shfl_xor_sync(0xFFFFFFFFu, sumA, 2);
        sumB += __shfl_xor_sync(0xFFFFFFFFu, sumB, 1);
        sumB += __shfl_xor_sync(0xFFFFFFFFu, sumB, 2);
        lrA = lrA * scA + sumA;
        lrB = lrB * scB + sumB;
#pragma unroll
        for (int n = 0; n < 16; ++n) {
            oacc[n][0] *= scA; oacc[n][1] *= scA;
            oacc[n][2] *= scB; oacc[n][3] *= scB;
        }
        __syncwarp();  // P rows are warp-private; make STS visible to warp's LDS

        // ---- O += Ph*Vh + Ph*Vl + Pl*Vh ----
#pragma unroll 2
        for (int ks = 0; ks < 8; ++ks) {
            const int ak = aoff + ks * 32;
            uint32_t ah[4], al[4];
            ah[0] = *reinterpret_cast<uint32_t*>(KH + ak);
            ah[1] = *reinterpret_cast<uint32_t*>(KH + ak + 2176);
            ah[2] = *reinterpret_cast<uint32_t*>(KH + ak + 16);
            ah[3] = *reinterpret_cast<uint32_t*>(KH + ak + 2176 + 16);
            al[0] = *reinterpret_cast<uint32_t*>(KL + ak);
            al[1] = *reinterpret_cast<uint32_t*>(KL + ak + 2176);
            al[2] = *reinterpret_cast<uint32_t*>(KL + ak + 16);
            al[3] = *reinterpret_cast<uint32_t*>(KL + ak + 2176 + 16);
#pragma unroll
            for (int n = 0; n < 16; ++n) {
                const int bk = boffg + n * 2176 + ks * 32;
                uint32_t bh0 = *reinterpret_cast<uint32_t*>(VH + bk);
                uint32_t bh1 = *reinterpret_cast<uint32_t*>(VH + bk + 16);
                uint32_t bl0 = *reinterpret_cast<uint32_t*>(VL + bk);
                uint32_t bl1 = *reinterpret_cast<uint32_t*>(VL + bk + 16);
                mma_bf16(oacc[n], ah, bh0, bh1);
                mma_bf16(oacc[n], ah, bl0, bl1);
                mma_bf16(oacc[n], al, bh0, bh1);
            }
        }
    }

    // ---- dump partial O (unnormalized, [q][m]) + (m, l) ----
    const size_t obase = ((size_t)((sp * BB + b) * NT + qt)) << 14;
#pragma unroll
    for (int n = 0; n < 16; ++n) {
        const int c = n * 8 + tt * 2;
        *reinterpret_cast<float2*>(&g_Op[obase + (size_t)rA * 128 + c]) =
            make_float2(oacc[n][0], oacc[n][1]);
        *reinterpret_cast<float2*>(&g_Op[obase + (size_t)(rA + 8) * 128 + c]) =
            make_float2(oacc[n][2], oacc[n][3]);
    }
    if (tt == 0) {
        const int mb = ((sp * BB + b) * NT + qt) * 256;
        g_ml[mb + rA]           = mrA;
        g_ml[mb + rA + 8]       = mrB;
        g_ml[mb + 128 + rA]     = lrA;
        g_ml[mb + 128 + rA + 8] = lrB;
    }
}

// ============================================================================
// Phase 3: merge splits + w4 epilogue + bias + residual (unchanged).
// ============================================================================
#define PAD 130
#define OS_OFF   0
#define W4_OFF   (128 * 130)
#define WS_OFF   (W4_OFF + 128 * 258)
#define INVL_OFF (WS_OFF + 3 * 128)
#define COMB_FLOATS (INVL_OFF + 128)

__global__ void __launch_bounds__(256, 1) combine_kernel(
    const float* __restrict__ x, const float* __restrict__ w4,
    const float* __restrict__ b4, float* __restrict__ out)
{
    extern __shared__ float smf[];
    float* Os   = smf + OS_OFF;
    float* w4s  = smf + W4_OFF;
    float* ws   = smf + WS_OFF;
    float* invl = smf + INVL_OFF;

    const int qt = blockIdx.x;
    const int b  = blockIdx.y;
    const int t  = threadIdx.x;

    if (t < 128) {
        float m0 = ninf(); float msv[SPLITS], lsv[SPLITS];
#pragma unroll
        for (int s = 0; s < SPLITS; ++s) {
            const int mb = ((s * BB + b) * NT + qt) * 256;
            msv[s] = g_ml[mb + t];
            lsv[s] = g_ml[mb + 128 + t];
            m0 = fmaxf(m0, msv[s]);
        }
        float lsum = 0.f;
#pragma unroll
        for (int s = 0; s < SPLITS; ++s) {
            float w = __expf(msv[s] - m0);
            ws[s * 128 + t] = w;
            lsum += lsv[s] * w;
        }
        invl[t] = 1.f / lsum;
    }
    for (int idx = t; idx < CC * MID; idx += 256) {
        int c = idx >> 7, m = idx & 127;
        w4s[m * 258 + c] = w4[idx];
    }
    __syncthreads();

    for (int idx = t; idx < 128 * 128; idx += 256) {
        int q = idx >> 7, m = idx & 127;
        float a = 0.f;
#pragma unroll
        for (int s = 0; s < SPLITS; ++s) {
            const size_t ob = ((size_t)((s * BB + b) * NT + qt)) << 14;
            a += g_Op[ob + idx] * ws[s * 128 + q];
        }
        Os[m * PAD + q] = a * invl[q];
    }
    __syncthreads();

    const int tc = t >> 4;
    const int tn = t & 15;
    unsigned long long e2[8][8];
#pragma unroll
    for (int v = 0; v < 8; ++v)
#pragma unroll
        for (int u = 0; u < 8; ++u) e2[v][u] = 0ULL;

#pragma unroll 4
    for (int m = 0; m < 128; ++m) {
        unsigned long long wv[8];
#pragma unroll
        for (int v = 0; v < 8; ++v)
            wv[v] = lds2(&w4s[m * 258 + tc * 16 + 2 * v]);
#pragma unroll
        for (int u = 0; u < 8; ++u) {
            float ov = Os[m * PAD + tn + 16 * u];
            unsigned long long ov2 = pack2(ov, ov);
#pragma unroll
            for (int v = 0; v < 8; ++v) fma2(e2[v][u], wv[v], ov2);
        }
    }

    const int n0 = qt * 128;
#pragma unroll
    for (int v = 0; v < 8; ++v) {
        int c = tc * 16 + 2 * v;
        float bv0 = b4[c], bv1 = b4[c + 1];
#pragma unroll
        for (int u = 0; u < 8; ++u) {
            float ex, ey; unpack2(e2[v][u], ex, ey);
            int q = tn + 16 * u;
            size_t i0 = (size_t)(b * CC + c) * NN + n0 + q;
            size_t i1 = i0 + NN;
            out[i0] = x[i0] + bv0 + ex;
            out[i1] = x[i1] + bv1 + ey;
        }
    }
}

// ============================================================================
extern "C" void kernel_launch(void* const* d_in, const int* in_sizes, int n_in,
                              void* d_out, int out_size)
{
    (void)in_sizes; (void)n_in; (void)out_size;
    const float* x  = (const float*)d_in[0];
    const float* w1 = (const float*)d_in[1];
    const float* b1 = (const float*)d_in[2];
    const float* w2 = (const float*)d_in[3];
    const float* b2 = (const float*)d_in[4];
    const float* w3 = (const float*)d_in[5];
    const float* b3 = (const float*)d_in[6];
    const float* w4 = (const float*)d_in[7];
    const float* b4 = (const float*)d_in[8];
    float* out = (float*)d_out;

    const int comb_smem = COMB_FLOATS * (int)sizeof(float);
    cudaFuncSetAttribute(attn_kernel, cudaFuncAttributeMaxDynamicSharedMemorySize, ATTN_SMEM);
    cudaFuncSetAttribute(combine_kernel, cudaFuncAttributeMaxDynamicSharedMemorySize, comb_smem);

    proj_kernel<<<dim3(NT, 12, BB), 64>>>(x, w1, b1, w2, b2, w3, b3);
    attn_kernel<<<dim3(NT, BB, SPLITS), 256, ATTN_SMEM>>>();
    combine_kernel<<<dim3(NT, BB), 256, comb_smem>>>(x, w4, b4, out);
}